// round 5
// baseline (speedup 1.0000x reference)
#include <cuda_runtime.h>
#include <cuda_bf16.h>

// HybridQLSTM_65481071409480 — GB300 (sm_103a)
//
// Algebraic collapse (verified, rel_err = 0.0 exactly):
//   log_softmax over a broadcast-constant row of length T=50 is identically
//   -log(50) for every output element, independent of ALL inputs. The
//   embedding gather, 512-step LSTM scan, and sin() expectation are dead
//   code. Output = fill of fp32 -log(50) over 819200 floats (3.125 MiB).
//
// R4 post-mortem: lean body (1 predicated STG.E.128/thread, 16 regs) cut
// kernel to 3.49us / total 4.61us; DRAM=0% so the ~0.3us store drain is not
// the cost — CTA dispatch ramp is. R5: same 204800 threads, 1 store each,
// but 200 CTAs x 1024 threads instead of 800 x 256 -> 4x fewer CTA
// dispatches in the ramp.

__global__ __launch_bounds__(1024)
void fill_neglog50_kernel(float4* __restrict__ out4, int n4,
                          float* __restrict__ out_tail, int n_tail) {
    const float v = -3.9120230674743652f;  // fp32-nearest -log(50)
    const int idx = blockIdx.x * blockDim.x + threadIdx.x;
    if (idx < n4) {
        out4[idx] = make_float4(v, v, v, v);
    }
    if (idx < n_tail) {                    // n_tail = 0 for this problem
        out_tail[idx] = v;
    }
}

extern "C" void kernel_launch(void* const* d_in, const int* in_sizes, int n_in,
                              void* d_out, int out_size) {
    (void)d_in; (void)in_sizes; (void)n_in;
    if (out_size <= 0) return;

    float* out = (float*)d_out;
    int n4 = out_size >> 2;            // 204800
    int n_tail = out_size & 3;         // 0
    float* tail_ptr = out + (size_t)n4 * 4;

    const int threads = 1024;
    int blocks = (n4 + threads - 1) / threads;  // 200
    if (blocks < 1) blocks = 1;

    fill_neglog50_kernel<<<blocks, threads>>>(
        (float4*)out, n4, tail_ptr, n_tail);
}

// round 7
// speedup vs baseline: 1.3819x; 1.3819x over previous
#include <cuda_runtime.h>
#include <cuda_bf16.h>

// HybridQLSTM_65481071409480 — GB300 (sm_103a)
//
// Algebraic collapse (verified on-HW, rel_err = 0.0 exactly):
//   log_softmax over a broadcast-constant row of length T=50 is identically
//   -log(50) for every output element, independent of ALL inputs. The whole
//   embedding/LSTM/sin pipeline is dead code. Output = fill of fp32 -log(50)
//   over 819200 floats (3.125 MiB).
//
// Empirical ordering (ncu kernel time): 800x256 lean 3.49us beats 800x256
// loopy (3.94), 200x1024 (4.29), 200CTAx4-stores (4.86). Many small CTAs,
// one STG.E.128 per thread, wins. This round (resubmit; R6 bench was an
// infra failure): host-side exact-fit dispatch removes both bound checks
// and the tail path from the hot kernel -> minimal body
// (S2R, IMAD, STG.E.128, EXIT). Guarded kernel kept as generic fallback.

__global__ __launch_bounds__(256)
void fill_neglog50_exact(float4* __restrict__ out4) {
    const float v = -3.9120230674743652f;  // fp32-nearest -log(50)
    const int idx = blockIdx.x * blockDim.x + threadIdx.x;
    out4[idx] = make_float4(v, v, v, v);   // exact-fit: no bounds check
}

__global__ __launch_bounds__(256)
void fill_neglog50_generic(float4* __restrict__ out4, int n4,
                           float* __restrict__ out_tail, int n_tail) {
    const float v = -3.9120230674743652f;
    const int idx = blockIdx.x * blockDim.x + threadIdx.x;
    if (idx < n4) {
        out4[idx] = make_float4(v, v, v, v);
    }
    if (idx < n_tail) {
        out_tail[idx] = v;
    }
}

extern "C" void kernel_launch(void* const* d_in, const int* in_sizes, int n_in,
                              void* d_out, int out_size) {
    (void)d_in; (void)in_sizes; (void)n_in;
    if (out_size <= 0) return;

    float* out = (float*)d_out;
    const int threads = 256;
    int n4 = out_size >> 2;            // 204800 for this problem
    int n_tail = out_size & 3;         // 0

    if (n_tail == 0 && n4 > 0 && (n4 % threads) == 0) {
        // Exact fit: 800 CTAs x 256 threads, one unguarded STG.E.128 each.
        fill_neglog50_exact<<<n4 / threads, threads>>>((float4*)out);
    } else {
        float* tail_ptr = out + (size_t)n4 * 4;
        int blocks = (n4 + threads - 1) / threads;
        if (blocks < 1) blocks = 1;
        fill_neglog50_generic<<<blocks, threads>>>(
            (float4*)out, n4, tail_ptr, n_tail);
    }
}